// round 13
// baseline (speedup 1.0000x reference)
#include <cuda_runtime.h>
#include <cuda_bf16.h>
#include <math.h>
#include <stdint.h>

// ---------------- problem constants ----------------
#define BB   2
#define SS   1024
#define DD   768
#define HH   12
#define DH   64
#define FF_  3072
#define LL   12
#define VV   50257
#define MR   2048          // B*S rows
#define D3   2304          // 3*D
#define NT   393           // ceil(VV/128) logits n-tiles
#define NQT  8             // q-tiles per (b,h)
#define NITEM (BB * HH * NQT)   // 192 flash items

// ---------------- scratch (static device memory) ----------------
__device__ float g_x   [MR * DD];
__device__ float g_picked[MR];
__device__ float g_pm  [MR * NT];
__device__ float g_ps  [MR * NT];
__device__ float g_opart[2 * NITEM * 8192];   // flash partial O (fp32)
__device__ float g_ml   [2 * NITEM * 256];    // flash partial (m,l)
__device__ unsigned int g_cnt[NITEM];          // arrival counters (self-resetting)

__device__ __nv_bfloat16 g_hb  [MR * DD];
__device__ __nv_bfloat16 g_ob  [MR * DD];
__device__ __nv_bfloat16 g_ffb [MR * FF_];
__device__ __nv_bfloat16 g_qkvb[MR * D3];

__device__ __nv_bfloat16 g_wteb [VV * DD];
__device__ __nv_bfloat16 g_qkvT [LL * DD * D3];
__device__ __nv_bfloat16 g_projT[LL * DD * DD];
__device__ __nv_bfloat16 g_fc1T [LL * DD * FF_];
__device__ __nv_bfloat16 g_fc2T [LL * FF_ * DD];

// ================= low-level helpers (baseline PTX only) =================
__device__ __forceinline__ uint32_t smem_u32(const void* p) {
    uint32_t a;
    asm("{ .reg .u64 t; cvta.to.shared.u64 t, %1; cvt.u32.u64 %0, t; }" : "=r"(a) : "l"(p));
    return a;
}
__device__ __forceinline__ void cp_async16(uint32_t dst, const void* src, bool valid) {
    int sz = valid ? 16 : 0;
    asm volatile("cp.async.cg.shared.global [%0], [%1], 16, %2;"
                 :: "r"(dst), "l"(src), "r"(sz) : "memory");
}
#define CP_COMMIT()  asm volatile("cp.async.commit_group;" ::: "memory")
#define CP_WAIT(n)   asm volatile("cp.async.wait_group %0;" :: "n"(n) : "memory")

__device__ __forceinline__ void ldmatrix_x4(uint32_t& r0, uint32_t& r1,
                                            uint32_t& r2, uint32_t& r3, uint32_t addr) {
    asm volatile("ldmatrix.sync.aligned.m8n8.x4.shared.b16 {%0,%1,%2,%3}, [%4];"
                 : "=r"(r0), "=r"(r1), "=r"(r2), "=r"(r3) : "r"(addr));
}
__device__ __forceinline__ void ldmatrix_x4_trans(uint32_t& r0, uint32_t& r1,
                                                  uint32_t& r2, uint32_t& r3, uint32_t addr) {
    asm volatile("ldmatrix.sync.aligned.m8n8.x4.trans.shared.b16 {%0,%1,%2,%3}, [%4];"
                 : "=r"(r0), "=r"(r1), "=r"(r2), "=r"(r3) : "r"(addr));
}
__device__ __forceinline__ void mma_bf16(float* c, const uint32_t* a,
                                         uint32_t b0, uint32_t b1) {
    asm volatile(
        "mma.sync.aligned.m16n8k16.row.col.f32.bf16.bf16.f32 "
        "{%0,%1,%2,%3}, {%4,%5,%6,%7}, {%8,%9}, {%0,%1,%2,%3};"
        : "+f"(c[0]), "+f"(c[1]), "+f"(c[2]), "+f"(c[3])
        : "r"(a[0]), "r"(a[1]), "r"(a[2]), "r"(a[3]), "r"(b0), "r"(b1));
}
__device__ __forceinline__ uint32_t pack_bf16x2(float lo, float hi) {
    __nv_bfloat162 h = __floats2bfloat162_rn(lo, hi);
    return *reinterpret_cast<uint32_t*>(&h);
}
__device__ __forceinline__ void ms_update(float& m, float& s, float v) {
    if (v > m) { s = s * __expf(m - v) + 1.0f; m = v; }
    else       { s += __expf(v - m); }
}
__device__ __forceinline__ void ms_combine(float& m, float& s, float m2, float s2) {
    float mn = fmaxf(m, m2);
    float e1 = (m  > -INFINITY) ? __expf(m  - mn) : 0.f;
    float e2 = (m2 > -INFINITY) ? __expf(m2 - mn) : 0.f;
    s = s * e1 + s2 * e2;
    m = mn;
}

// ---------------- block reductions ----------------
__device__ __forceinline__ float blockReduceSum(float v) {
    __shared__ float sh[32];
    int lane = threadIdx.x & 31, wid = threadIdx.x >> 5;
    #pragma unroll
    for (int o = 16; o; o >>= 1) v += __shfl_xor_sync(0xffffffffu, v, o);
    __syncthreads();
    if (lane == 0) sh[wid] = v;
    __syncthreads();
    float r = (lane < (int)(blockDim.x >> 5)) ? sh[lane] : 0.f;
    if (wid == 0) {
        #pragma unroll
        for (int o = 16; o; o >>= 1) r += __shfl_xor_sync(0xffffffffu, r, o);
        if (lane == 0) sh[0] = r;
    }
    __syncthreads();
    return sh[0];
}
__device__ __forceinline__ float2 blockReduceSum2(float a, float b) {
    __shared__ float2 sh[8];
    int lane = threadIdx.x & 31, wid = threadIdx.x >> 5;
    #pragma unroll
    for (int o = 16; o; o >>= 1) {
        a += __shfl_xor_sync(0xffffffffu, a, o);
        b += __shfl_xor_sync(0xffffffffu, b, o);
    }
    if (lane == 0) sh[wid] = make_float2(a, b);
    __syncthreads();
    if (wid == 0) {
        float2 r = (lane < 8) ? sh[lane] : make_float2(0.f, 0.f);
        #pragma unroll
        for (int o = 4; o; o >>= 1) {
            r.x += __shfl_xor_sync(0xffffffffu, r.x, o);
            r.y += __shfl_xor_sync(0xffffffffu, r.y, o);
        }
        if (lane == 0) sh[0] = r;
    }
    __syncthreads();
    return sh[0];
}

// ---------------- weight prep ----------------
__global__ void transpose_to_bf16(const float* __restrict__ src,
                                  __nv_bfloat16* __restrict__ dst,
                                  int K, int N) {
    __shared__ float tile[64][65];
    const float* s = src + (size_t)blockIdx.z * K * N;
    __nv_bfloat16* d = dst + (size_t)blockIdx.z * K * N;
    int n0 = blockIdx.x * 64, k0 = blockIdx.y * 64;
    int tid = threadIdx.x;
    #pragma unroll
    for (int e = 0; e < 8; e++) {
        int idx = tid + e * 256;
        int r = idx >> 5, c = idx & 31;
        float2 v = *reinterpret_cast<const float2*>(s + (size_t)(k0 + r) * N + n0 + c * 2);
        tile[c * 2][r]     = v.x;
        tile[c * 2 + 1][r] = v.y;
    }
    __syncthreads();
    #pragma unroll
    for (int e = 0; e < 8; e++) {
        int idx = tid + e * 256;
        int r = idx >> 5, c = (idx & 31) * 2;
        __nv_bfloat162 v = __floats2bfloat162_rn(tile[r][c], tile[r][c + 1]);
        *reinterpret_cast<__nv_bfloat162*>(d + (size_t)(n0 + r) * K + k0 + c) = v;
    }
}

__global__ void convert_bf16_kernel4(const float4* __restrict__ src,
                                     __nv_bfloat162* __restrict__ dst, long n4) {
    long i = (long)blockIdx.x * blockDim.x + threadIdx.x;
    if (i < n4) {
        float4 v = src[i];
        dst[i * 2]     = __floats2bfloat162_rn(v.x, v.y);
        dst[i * 2 + 1] = __floats2bfloat162_rn(v.z, v.w);
    }
}

// ---------------- embedding (float2) ----------------
__global__ void embed_kernel(const int* __restrict__ tokens,
                             const float* __restrict__ wte,
                             const float* __restrict__ wpe,
                             float* __restrict__ x) {
    int i = blockIdx.x * blockDim.x + threadIdx.x;   // over MR * 384 pairs
    if (i >= MR * (DD / 2)) return;
    int row = i / (DD / 2), d2 = i - row * (DD / 2);
    int s = row & (SS - 1);
    float2 a = *reinterpret_cast<const float2*>(wte + (size_t)tokens[row] * DD + d2 * 2);
    float2 b = *reinterpret_cast<const float2*>(wpe + (size_t)s * DD + d2 * 2);
    *reinterpret_cast<float2*>(x + (size_t)row * DD + d2 * 2) = make_float2(a.x + b.x, a.y + b.y);
}

// ---------------- layernorm -> bf16 ----------------
__global__ void layernorm_kernel(const float* __restrict__ in,
                                 const float* __restrict__ g,
                                 const float* __restrict__ b,
                                 __nv_bfloat16* __restrict__ out) {
    int row = blockIdx.x;
    const float* x = in + (size_t)row * DD;
    int t = threadIdx.x;
    float v0 = x[t], v1 = x[t + 256], v2 = x[t + 512];
    float2 r = blockReduceSum2(v0 + v1 + v2, v0 * v0 + v1 * v1 + v2 * v2);
    float mu = r.x * (1.0f / 768.0f);
    float var = r.y * (1.0f / 768.0f) - mu * mu;
    float rstd = rsqrtf(var + 1e-5f);
    __nv_bfloat16* o = out + (size_t)row * DD;
    o[t]       = __float2bfloat16((v0 - mu) * rstd * g[t]       + b[t]);
    o[t + 256] = __float2bfloat16((v1 - mu) * rstd * g[t + 256] + b[t + 256]);
    o[t + 512] = __float2bfloat16((v2 - mu) * rstd * g[t + 512] + b[t + 512]);
}

// ================= mma.sync NT GEMM, single-barrier 3-stage pipeline ========
#define GBM 128
#define GBK 64
#define ROWB 144
#define ABUF 18432   // 128 * 144

template <bool FUSE, int BN, bool ATOMIC>
__global__ __launch_bounds__(256, 2)
void gemm_mma_kernel(const __nv_bfloat16* __restrict__ A,
                     const __nv_bfloat16* __restrict__ B,
                     float* __restrict__ Cf,
                     __nv_bfloat16* __restrict__ Cbf,
                     const float* __restrict__ bias,
                     const float* __restrict__ res,
                     int N, int K, int ldc, int act,
                     float* __restrict__ pm, float* __restrict__ ps) {
    constexpr int BBUF = BN * ROWB;
    constexpr int BUFS = ABUF + BBUF;
    constexpr int NNB  = BN / 32;
    extern __shared__ __align__(128) uint8_t gsm[];
    uint32_t sbase = smem_u32(gsm);
    int tid = threadIdx.x;
    int m0 = blockIdx.x * GBM, n0 = blockIdx.y * BN;
    int nk = K / GBK;
    int kbase = 0;
    if (ATOMIC) {
        nk = K / GBK / gridDim.z;
        kbase = blockIdx.z * nk;
    }

    auto issue = [&](int c) {
        int k0 = (kbase + c) * GBK;
        int st = c % 3;
        uint32_t dA = sbase + st * BUFS;
        uint32_t dB = dA + ABUF;
        #pragma unroll
        for (int e = 0; e < 4; e++) {
            int idx = tid + e * 256;
            int r = idx >> 3, cc = idx & 7;
            cp_async16(dA + r * ROWB + cc * 16,
                       A + (size_t)(m0 + r) * K + k0 + cc * 8, true);
        }
        #pragma unroll
        for (int e = 0; e < BN / 32; e++) {
            int idx = tid + e * 256;
            int r = idx >> 3, cc = idx & 7;
            int gn = n0 + r;
            cp_async16(dB + r * ROWB + cc * 16,
                       B + (size_t)gn * K + k0 + cc * 8, gn < N);
        }
        CP_COMMIT();
    };

    int warp = tid >> 5, lane = tid & 31;
    int wm = warp >> 1, wn = warp & 1;
    int lr = lane & 15, lc = lane >> 4;
    float acc[2][2 * NNB][4];
    #pragma unroll
    for (int i = 0; i < 2; i++)
        #pragma unroll
        for (int j = 0; j < 2 * NNB; j++)
            #pragma unroll
            for (int q = 0; q < 4; q++) acc[i][j][q] = 0.f;

    issue(0);
    if (nk > 1) issue(1);
    for (int c = 0; c < nk; c++) {
        if (c + 1 < nk) { CP_WAIT(1); } else { CP_WAIT(0); }
        __syncthreads();
        uint32_t aB = sbase + (c % 3) * BUFS;
        uint32_t bB = aB + ABUF;
        #pragma unroll
        for (int kk = 0; kk < 4; kk++) {
            uint32_t a[2][4];
            #pragma unroll
            for (int mi = 0; mi < 2; mi++) {
                uint32_t addr = aB + (uint32_t)((wm * 32 + mi * 16 + lr) * ROWB
                                                + (kk * 16 + lc * 8) * 2);
                ldmatrix_x4(a[mi][0], a[mi][1], a[mi][2], a[mi][3], addr);
            }
            #pragma unroll
            for (int nb = 0; nb < NNB; nb++) {
                uint32_t b0, b1, b2, b3;
                uint32_t addr = bB + (uint32_t)((wn * (BN / 2) + nb * 16 + lr) * ROWB
                                                + (kk * 16 + lc * 8) * 2);
                ldmatrix_x4(b0, b1, b2, b3, addr);
                #pragma unroll
                for (int mi = 0; mi < 2; mi++) {
                    mma_bf16(acc[mi][nb * 2],     a[mi], b0, b2);
                    mma_bf16(acc[mi][nb * 2 + 1], a[mi], b1, b3);
                }
            }
        }
        if (c + 2 < nk) issue(c + 2);
    }

    // --- epilogue ---
    int mrow = m0 + wm * 32;
    int ncol = n0 + wn * (BN / 2);
    int tr = lane >> 2, tc = (lane & 3) * 2;
    bool vec = ((ldc & 1) == 0);
    float tm[2][2], ts[2][2];
    if (FUSE) {
        #pragma unroll
        for (int i = 0; i < 2; i++)
            #pragma unroll
            for (int j = 0; j < 2; j++) { tm[i][j] = -INFINITY; ts[i][j] = 0.f; }
    }
    #pragma unroll
    for (int mi = 0; mi < 2; mi++) {
        #pragma unroll
        for (int ni = 0; ni < 2 * NNB; ni++) {
            #pragma unroll
            for (int h = 0; h < 2; h++) {
                int row = mrow + mi * 16 + tr + h * 8;
                int col = ncol + ni * 8 + tc;
                float v0 = acc[mi][ni][h * 2];
                float v1 = acc[mi][ni][h * 2 + 1];
                if (ATOMIC) {
                    if (bias && blockIdx.z == 0) {
                        v0 += bias[col];
                        if (col + 1 < N) v1 += bias[col + 1];
                    }
                    if (col < N)     atomicAdd(Cf + (size_t)row * ldc + col, v0);
                    if (col + 1 < N) atomicAdd(Cf + (size_t)row * ldc + col + 1, v1);
                    continue;
                }
                if (bias) { v0 += bias[col]; if (col + 1 < N) v1 += bias[col + 1]; }
                if (res) {
                    const float* rp = res + (size_t)row * ldc + col;
                    v0 += rp[0];
                    if (col + 1 < N) v1 += rp[1];
                }
                if (act) {
                    v0 = v0 * 0.5f * (1.0f + erff(v0 * 0.70710678118654752f));
                    v1 = v1 * 0.5f * (1.0f + erff(v1 * 0.70710678118654752f));
                }
                if (FUSE) {
                    if (col < N)     ms_update(tm[mi][h], ts[mi][h], v0);
                    if (col + 1 < N) ms_update(tm[mi][h], ts[mi][h], v1);
                }
                if (vec && col + 1 < N) {
                    if (Cf) *reinterpret_cast<float2*>(Cf + (size_t)row * ldc + col)
                                = make_float2(v0, v1);
                    else    *reinterpret_cast<__nv_bfloat162*>(Cbf + (size_t)row * ldc + col)
                                = __floats2bfloat162_rn(v0, v1);
                } else {
                    if (col < N) {
                        if (Cf) Cf[(size_t)row * ldc + col] = v0;
                        else    Cbf[(size_t)row * ldc + col] = __float2bfloat16(v0);
                    }
                    if (col + 1 < N) {
                        if (Cf) Cf[(size_t)row * ldc + col + 1] = v1;
                        else    Cbf[(size_t)row * ldc + col + 1] = __float2bfloat16(v1);
                    }
                }
            }
        }
    }
    if (FUSE) {
        float2* red = reinterpret_cast<float2*>(gsm);
        __syncthreads();
        #pragma unroll
        for (int mi = 0; mi < 2; mi++) {
            #pragma unroll
            for (int h = 0; h < 2; h++) {
                float m = tm[mi][h], s = ts[mi][h];
                #pragma unroll
                for (int o = 1; o <= 2; o <<= 1) {
                    float m2 = __shfl_xor_sync(0xffffffffu, m, o);
                    float s2 = __shfl_xor_sync(0xffffffffu, s, o);
                    ms_combine(m, s, m2, s2);
                }
                if ((lane & 3) == 0) {
                    int row_local = wm * 32 + mi * 16 + tr + h * 8;
                    red[row_local * 2 + wn] = make_float2(m, s);
                }
            }
        }
        __syncthreads();
        if (tid < 128) {
            float2 p0 = red[tid * 2], p1 = red[tid * 2 + 1];
            float m = p0.x, s = p0.y;
            ms_combine(m, s, p1.x, p1.y);
            pm[(size_t)(m0 + tid) * NT + blockIdx.y] = m;
            ps[(size_t)(m0 + tid) * NT + blockIdx.y] = s;
        }
    }
}

#define GS128 (3 * (ABUF + 128 * ROWB))   // 110592
#define GS64  (3 * (ABUF + 64 * ROWB))    // 82944

// ===== flash attention: split-KV partial + fused last-CTA merge =============
#define FQROWB 144
#define FQ_OFF 0
#define FKV_OFF 18432
#define FSTAGE  18432
#define FSMEM   (FKV_OFF + 3 * FSTAGE)   // 73728

__global__ __launch_bounds__(256, 2)
void flash_attn_kernel(const __nv_bfloat16* __restrict__ qkv,
                       float* __restrict__ opart,
                       float* __restrict__ mlout,
                       unsigned int* __restrict__ cnt,
                       __nv_bfloat16* __restrict__ o) {
    extern __shared__ __align__(128) uint8_t fsm[];
    uint32_t sbase = smem_u32(fsm);
    int tid = threadIdx.x;
    int qt = blockIdx.x;
    int q0 = qt * 128;
    int bh = blockIdx.y, b = bh / HH, h = bh - b * HH;
    int split = blockIdx.z;
    const size_t rowbase = (size_t)b * SS * D3;
    const int qoff = h * DH, koff = DD + h * DH, voff = 2 * DD + h * DH;

    int nt = q0 / 64 + 2;         // always even
    int nh = nt >> 1;
    int ts = split * nh, te = ts + nh;

    auto issue_q = [&]() {
        #pragma unroll
        for (int e = 0; e < 4; e++) {
            int idx = tid + e * 256;
            int r = idx >> 3, c = idx & 7;
            cp_async16(sbase + FQ_OFF + r * FQROWB + c * 16,
                       qkv + rowbase + (size_t)(q0 + r) * D3 + qoff + c * 8, true);
        }
        CP_COMMIT();
    };
    auto issue_kv = [&](int t) {
        int kv0 = t * 64;
        uint32_t kd = sbase + FKV_OFF + ((t - ts) % 3) * FSTAGE;
        uint32_t vd = kd + 9216;
        #pragma unroll
        for (int e = 0; e < 2; e++) {
            int idx = tid + e * 256;
            int r = idx >> 3, c = idx & 7;
            const size_t g = rowbase + (size_t)(kv0 + r) * D3;
            cp_async16(kd + r * FQROWB + c * 16, qkv + g + koff + c * 8, true);
            cp_async16(vd + r * FQROWB + c * 16, qkv + g + voff + c * 8, true);
        }
        CP_COMMIT();
    };

    int warp = tid >> 5, lane = tid & 31;
    int lr = lane & 15, lc = lane >> 4;
    int tr = lane >> 2, qd = lane & 3;
    int wq = q0 + warp * 16;

    float of[8][4];
    #pragma unroll
    for (int i = 0; i < 8; i++)
        #pragma unroll
        for (int j = 0; j < 4; j++) of[i][j] = 0.f;
    float m0r = -INFINITY, m1r = -INFINITY, l0r = 0.f, l1r = 0.f;

    issue_q();
    issue_kv(ts);
    if (te - ts > 1) issue_kv(ts + 1);

    const float sc = 0.03608439182435161f;  // 1/sqrt(768)

    for (int t = ts; t < te; t++) {
        if (t + 1 < te) { CP_WAIT(1); } else { CP_WAIT(0); }
        __syncthreads();
        int kv0 = t * 64;
        uint32_t kB = sbase + FKV_OFF + ((t - ts) % 3) * FSTAGE;
        uint32_t vB = kB + 9216;

        float sf[8][4];
        #pragma unroll
        for (int i = 0; i < 8; i++)
            #pragma unroll
            for (int j = 0; j < 4; j++) sf[i][j] = 0.f;
        #pragma unroll
        for (int ks = 0; ks < 4; ks++) {
            uint32_t aq[4];
            uint32_t qa = sbase + FQ_OFF + (uint32_t)((warp * 16 + lr) * FQROWB
                                                      + (ks * 16 + lc * 8) * 2);
            ldmatrix_x4(aq[0], aq[1], aq[2], aq[3], qa);
            #pragma unroll
            for (int nb2 = 0; nb2 < 4; nb2++) {
                uint32_t b0, b1, b2, b3;
                uint32_t ka = kB + (uint32_t)((nb2 * 16 + lr) * FQROWB
                                              + (ks * 16 + lc * 8) * 2);
                ldmatrix_x4(b0, b1, b2, b3, ka);
                mma_bf16(sf[nb2 * 2],     aq, b0, b2);
                mma_bf16(sf[nb2 * 2 + 1], aq, b1, b3);
            }
        }
        #pragma unroll
        for (int i = 0; i < 8; i++)
            #pragma unroll
            for (int j = 0; j < 4; j++) sf[i][j] *= sc;
        if (kv0 + 63 > wq) {
            #pragma unroll
            for (int nb = 0; nb < 8; nb++) {
                #pragma unroll
                for (int j = 0; j < 4; j++) {
                    int col = kv0 + nb * 8 + qd * 2 + (j & 1);
                    int row = wq + tr + (j >> 1) * 8;
                    if (col > row) sf[nb][j] = -INFINITY;
                }
            }
        }
        float tm0 = -INFINITY, tm1 = -INFINITY;
        #pragma unroll
        for (int nb = 0; nb < 8; nb++) {
            tm0 = fmaxf(tm0, fmaxf(sf[nb][0], sf[nb][1]));
            tm1 = fmaxf(tm1, fmaxf(sf[nb][2], sf[nb][3]));
        }
        tm0 = fmaxf(tm0, __shfl_xor_sync(0xffffffffu, tm0, 1));
        tm0 = fmaxf(tm0, __shfl_xor_sync(0xffffffffu, tm0, 2));
        tm1 = fmaxf(tm1, __shfl_xor_sync(0xffffffffu, tm1, 1));
        tm1 = fmaxf(tm1, __shfl_xor_sync(0xffffffffu, tm1, 2));
        float mn0 = fmaxf(m0r, tm0), mn1 = fmaxf(m1r, tm1);
        float mnc0 = fmaxf(mn0, -1e30f), mnc1 = fmaxf(mn1, -1e30f);
        float f0 = __expf(m0r - mnc0), f1 = __expf(m1r - mnc1);
        m0r = mn0; m1r = mn1;
        float rs0 = 0.f, rs1 = 0.f;
        #pragma unroll
        for (int nb = 0; nb < 8; nb++) {
            sf[nb][0] = __expf(sf[nb][0] - mnc0);
            sf[nb][1] = __expf(sf[nb][1] - mnc0);
            sf[nb][2] = __expf(sf[nb][2] - mnc1);
            sf[nb][3] = __expf(sf[nb][3] - mnc1);
            rs0 += sf[nb][0] + sf[nb][1];
            rs1 += sf[nb][2] + sf[nb][3];
        }
        rs0 += __shfl_xor_sync(0xffffffffu, rs0, 1);
        rs0 += __shfl_xor_sync(0xffffffffu, rs0, 2);
        rs1 += __shfl_xor_sync(0xffffffffu, rs1, 1);
        rs1 += __shfl_xor_sync(0xffffffffu, rs1, 2);
        l0r = l0r * f0 + rs0;
        l1r = l1r * f1 + rs1;
        #pragma unroll
        for (int nb = 0; nb < 8; nb++) {
            of[nb][0] *= f0; of[nb][1] *= f0;
            of[nb][2] *= f1; of[nb][3] *= f1;
        }
        #pragma unroll
        for (int ks = 0; ks < 4; ks++) {
            uint32_t ap[4];
            ap[0] = pack_bf16x2(sf[2 * ks][0],     sf[2 * ks][1]);
            ap[1] = pack_bf16x2(sf[2 * ks][2],     sf[2 * ks][3]);
            ap[2] = pack_bf16x2(sf[2 * ks + 1][0], sf[2 * ks + 1][1]);
            ap[3] = pack_bf16x2(sf[2 * ks + 1][2], sf[2 * ks + 1][3]);
            #pragma unroll
            for (int nb2 = 0; nb2 < 4; nb2++) {
                int g = lane >> 3;
                int kvr = ks * 16 + (g & 1) * 8 + (lane & 7);
                int dhc = nb2 * 16 + (g >> 1) * 8;
                uint32_t va = vB + (uint32_t)(kvr * FQROWB + dhc * 2);
                uint32_t r0, r1, r2, r3;
                ldmatrix_x4_trans(r0, r1, r2, r3, va);
                mma_bf16(of[nb2 * 2],     ap, r0, r1);
                mma_bf16(of[nb2 * 2 + 1], ap, r2, r3);
            }
        }
        if (t + 2 < te) issue_kv(t + 2);
    }

    // ---- write unnormalized partials ----
    int item = bh * NQT + qt;
    float* op = opart + ((size_t)split * NITEM + item) * 8192;
    float* ml = mlout + ((size_t)split * NITEM + item) * 256;
    #pragma unroll
    for (int nb = 0; nb < 8; nb++) {
        int col = nb * 8 + qd * 2;
        int r0 = warp * 16 + tr, r1 = r0 + 8;
        *reinterpret_cast<float2*>(op + r0 * 64 + col) = make_float2(of[nb][0], of[nb][1]);
        *reinterpret_cast<float2*>(op + r1 * 64 + col) = make_float2(of[nb][2], of[nb][3]);
    }
    if (qd == 0) {
        int r0 = warp * 16 + tr, r1 = r0 + 8;
        *reinterpret_cast<float2*>(ml + r0 * 2) = make_float2(m0r, l0r);
        *reinterpret_cast<float2*>(ml + r1 * 2) = make_float2(m1r, l1r);
    }

    // ---- last-CTA-merges handshake ----
    __shared__ unsigned int s_last;
    __threadfence();
    __syncthreads();
    if (tid == 0) s_last = atomicAdd(&cnt[item], 1u);
    __syncthreads();
    if (s_last != 1u) return;     // first arrival exits; second merges
    __threadfence();              // acquire: other CTA's partials now visible

    __shared__ float sf0[128], sf1[128], sinv[128];
    if (tid < 128) {
        float2 p0 = *reinterpret_cast<const float2*>(mlout + (size_t)item * 256 + tid * 2);
        float2 p1 = *reinterpret_cast<const float2*>(mlout + ((size_t)NITEM + item) * 256 + tid * 2);
        float m = fmaxf(p0.x, p1.x);
        float e0 = (p0.x > -1e30f) ? __expf(p0.x - m) : 0.f;
        float e1 = (p1.x > -1e30f) ? __expf(p1.x - m) : 0.f;
        float l = p0.y * e0 + p1.y * e1;
        sf0[tid] = e0; sf1[tid] = e1; sinv[tid] = 1.0f / l;
    }
    __syncthreads();
    const float* O0 = opart + (size_t)item * 8192;
    const float* O1 = opart + ((size_t)NITEM + item) * 8192;
    size_t obase = (size_t)b * SS * DD + (size_t)q0 * DD + (size_t)h * DH;
    for (int e = tid; e < 4096; e += 256) {
        int row = e >> 5, cp = (e & 31) * 2;
        float2 a = *reinterpret_cast<const float2*>(O0 + row * 64 + cp);
        float2 c = *reinterpret_cast<const float2*>(O1 + row * 64 + cp);
        float w0 = sf0[row], w1 = sf1[row], iv = sinv[row];
        __nv_bfloat162 v = __floats2bfloat162_rn((a.x * w0 + c.x * w1) * iv,
                                                 (a.y * w0 + c.y * w1) * iv);
        *reinterpret_cast<__nv_bfloat162*>(o + obase + (size_t)row * DD + cp) = v;
    }
    __syncthreads();
    if (tid == 0) cnt[item] = 0u;   // self-reset for next layer / graph replay
}

// ---- finish log_softmax from GEMM partials ---------------------------------
__global__ __launch_bounds__(512)
void logsoftmax_finish_kernel(float* __restrict__ logits,
                              const float* __restrict__ pm,
                              const float* __restrict__ ps,
                              const int* __restrict__ target,
                              float* __restrict__ picked) {
    __shared__ float shm[16], shs[16], bc[1];
    int row = blockIdx.x;
    float* x = logits + (size_t)row * VV;
    int t = threadIdx.x, lane = t & 31, wid = t >> 5;

    float m = -INFINITY, s = 0.f;
    const float* pmr = pm + (size_t)row * NT;
    const float* psr = ps + (size_t)row * NT;
    for (int i = t; i < NT; i += 512)
        ms_combine(m, s, pmr[i], psr[i]);
    #pragma unroll
    for (int o = 16; o; o >>= 1) {
        float m2 = __shfl_xor_sync(0xffffffffu, m, o);
        float s2 = __shfl_xor_sync(0xffffffffu, s, o);
        ms_combine(m, s, m2, s2);
    }
    if (lane == 0) { shm[wid] = m; shs[wid] = s; }
    __syncthreads();
    if (t == 0) {
        float M = shm[0], S = shs[0];
        #pragma unroll
        for (int i = 1; i < 16; i++)
            ms_combine(M, S, shm[i], shs[i]);
        bc[0] = M + logf(S);
    }
    __syncthreads();
    float sub = bc[0];
    int tgt = target[row];

    int head = (int)(((16 - ((uintptr_t)x & 15)) & 15) >> 2);
    int nvec = (VV - head) >> 2;
    float* xv = x + head;
    for (int i = t; i < head; i += 512) {
        float lp = x[i] - sub;
        x[i] = lp;
        if (i == tgt) picked[row] = lp;
    }
    for (int i = t; i < nvec; i += 512) {
        float4 v = *reinterpret_cast<const float4*>(xv + i * 4);
        v.x -= sub; v.y -= sub; v.z -= sub; v.w -= sub;
        *reinterpret_cast<float4*>(xv + i * 4) = v;
        int base = head + i * 4;
        if (tgt >= base && tgt < base + 4) {
            float pv = (tgt == base) ? v.x : (tgt == base + 1) ? v.y
                     : (tgt == base + 2) ? v.z : v.w;
            picked[row] = pv;
        }
    }
    for (int i = head + nvec * 4 + t; i < VV; i += 512) {
        float lp = x[i] - sub;
        x[i] = lp;
        if (i == tgt) picked[row] = lp;
    }
}

__global__ void finalize_loss_kernel(const float* __restrict__ picked,
                                     float* __restrict__ out) {
    float s = 0.f;
    for (int i = threadIdx.x; i < MR; i += 256) s += picked[i];
    s = blockReduceSum(s);
    if (threadIdx.x == 0) out[(size_t)MR * VV] = -s * (1.0f / (float)MR);
}

// ---------------- host orchestration ----------------
extern "C" void kernel_launch(void* const* d_in, const int* in_sizes, int n_in,
                              void* d_out, int out_size) {
    const int*   tokens = (const int*)  d_in[0];
    const int*   target = (const int*)  d_in[1];
    const float* wte    = (const float*)d_in[2];
    const float* wpe    = (const float*)d_in[3];
    const float* ln1_g  = (const float*)d_in[4];
    const float* ln1_b  = (const float*)d_in[5];
    const float* qkv_w  = (const float*)d_in[6];
    const float* qkv_b  = (const float*)d_in[7];
    const float* proj_w = (const float*)d_in[8];
    const float* proj_b = (const float*)d_in[9];
    const float* ln2_g  = (const float*)d_in[10];
    const float* ln2_b  = (const float*)d_in[11];
    const float* fc1_w  = (const float*)d_in[12];
    const float* fc1_b  = (const float*)d_in[13];
    const float* fc2_w  = (const float*)d_in[14];
    const float* fc2_b  = (const float*)d_in[15];
    const float* lnf_g  = (const float*)d_in[16];
    const float* lnf_b  = (const float*)d_in[17];
    float* out = (float*)d_out;

    float *gx, *gpicked, *gpm, *gps, *gopart, *gml;
    unsigned int* gcnt;
    __nv_bfloat16 *ghb, *gob, *gffb, *gqkvb, *gwteb, *gqkvT, *gprojT, *gfc1T, *gfc2T;
    cudaGetSymbolAddress((void**)&gx,     g_x);
    cudaGetSymbolAddress((void**)&gpicked,g_picked);
    cudaGetSymbolAddress((void**)&gpm,    g_pm);
    cudaGetSymbolAddress((void**)&gps,    g_ps);
    cudaGetSymbolAddress((void**)&gopart, g_opart);
    cudaGetSymbolAddress((void**)&gml,    g_ml);
    cudaGetSymbolAddress((void**)&gcnt,   g_cnt);
    cudaGetSymbolAddress((void**)&ghb,    g_hb);
    cudaGetSymbolAddress((void**)&gob,    g_ob);
    cudaGetSymbolAddress((void**)&gffb,   g_ffb);
    cudaGetSymbolAddress((void**)&gqkvb,  g_qkvb);
    cudaGetSymbolAddress((void**)&gwteb,  g_wteb);
    cudaGetSymbolAddress((void**)&gqkvT,  g_qkvT);
    cudaGetSymbolAddress((void**)&gprojT, g_projT);
    cudaGetSymbolAddress((void**)&gfc1T,  g_fc1T);
    cudaGetSymbolAddress((void**)&gfc2T,  g_fc2T);

    cudaFuncSetAttribute(flash_attn_kernel,
                         cudaFuncAttributeMaxDynamicSharedMemorySize, FSMEM);
    cudaFuncSetAttribute(gemm_mma_kernel<false, 128, false>,
                         cudaFuncAttributeMaxDynamicSharedMemorySize, GS128);
    cudaFuncSetAttribute(gemm_mma_kernel<true, 128, false>,
                         cudaFuncAttributeMaxDynamicSharedMemorySize, GS128);
    cudaFuncSetAttribute(gemm_mma_kernel<false, 64, false>,
                         cudaFuncAttributeMaxDynamicSharedMemorySize, GS64);
    cudaFuncSetAttribute(gemm_mma_kernel<false, 64, true>,
                         cudaFuncAttributeMaxDynamicSharedMemorySize, GS64);

    {
        long n4 = (long)VV * DD / 4;
        convert_bf16_kernel4<<<(int)((n4 + 255) / 256), 256>>>(
            (const float4*)wte, (__nv_bfloat162*)gwteb, n4);
    }
    transpose_to_bf16<<<dim3(D3 / 64,  DD / 64,  LL), 256>>>(qkv_w,  gqkvT,  DD,  D3);
    transpose_to_bf16<<<dim3(DD / 64,  DD / 64,  LL), 256>>>(proj_w, gprojT, DD,  DD);
    transpose_to_bf16<<<dim3(FF_ / 64, DD / 64,  LL), 256>>>(fc1_w,  gfc1T,  DD,  FF_);
    transpose_to_bf16<<<dim3(DD / 64,  FF_ / 64, LL), 256>>>(fc2_w,  gfc2T,  FF_, DD);

    embed_kernel<<<(MR * (DD / 2) + 255) / 256, 256>>>(tokens, wte, wpe, gx);

    for (int l = 0; l < LL; l++) {
        layernorm_kernel<<<MR, 256>>>(gx, ln1_g + (size_t)l * DD, ln1_b + (size_t)l * DD, ghb);

        gemm_mma_kernel<false, 128, false><<<dim3(MR / GBM, D3 / 128), 256, GS128>>>(
            ghb, gqkvT + (size_t)l * DD * D3, nullptr, gqkvb,
            qkv_b + (size_t)l * D3, nullptr, D3, DD, D3, 0, nullptr, nullptr);

        flash_attn_kernel<<<dim3(NQT, BB * HH, 2), 256, FSMEM>>>(
            gqkvb, gopart, gml, gcnt, gob);

        gemm_mma_kernel<false, 64, true><<<dim3(MR / GBM, DD / 64, 2), 256, GS64>>>(
            gob, gprojT + (size_t)l * DD * DD, gx, nullptr,
            proj_b + (size_t)l * DD, nullptr, DD, DD, DD, 0, nullptr, nullptr);

        layernorm_kernel<<<MR, 256>>>(gx, ln2_g + (size_t)l * DD, ln2_b + (size_t)l * DD, ghb);

        gemm_mma_kernel<false, 64, false><<<dim3(MR / GBM, FF_ / 64), 256, GS64>>>(
            ghb, gfc1T + (size_t)l * DD * FF_, nullptr, gffb,
            fc1_b + (size_t)l * FF_, nullptr, FF_, DD, FF_, 1, nullptr, nullptr);

        gemm_mma_kernel<false, 64, true><<<dim3(MR / GBM, DD / 64, 2), 256, GS64>>>(
            gffb, gfc2T + (size_t)l * FF_ * DD, gx, nullptr,
            fc2_b + (size_t)l * DD, nullptr, DD, FF_, DD, 0, nullptr, nullptr);
    }

    layernorm_kernel<<<MR, 256>>>(gx, lnf_g, lnf_b, ghb);

    gemm_mma_kernel<true, 128, false><<<dim3(MR / GBM, NT), 256, GS128>>>(
        ghb, gwteb, out, nullptr, nullptr, nullptr, VV, DD, VV, 0, gpm, gps);

    logsoftmax_finish_kernel<<<MR, 512>>>(out, gpm, gps, target, gpicked);
    finalize_loss_kernel<<<1, 256>>>(gpicked, out);
}

// round 14
// speedup vs baseline: 1.0309x; 1.0309x over previous
#include <cuda_runtime.h>
#include <cuda_bf16.h>
#include <math.h>
#include <stdint.h>

// ---------------- problem constants ----------------
#define BB   2
#define SS   1024
#define DD   768
#define HH   12
#define DH   64
#define FF_  3072
#define LL   12
#define VV   50257
#define MR   2048          // B*S rows
#define D3   2304          // 3*D
#define NT   393           // ceil(VV/128) logits n-tiles
#define NQT  8             // q-tiles per (b,h)
#define NITEM (BB * HH * NQT)   // 192 flash items

// ---------------- scratch (static device memory) ----------------
__device__ float g_x   [MR * DD];
__device__ float g_picked[MR];
__device__ float g_pm  [MR * NT];
__device__ float g_ps  [MR * NT];
__device__ float g_opart[2 * NITEM * 8192];   // flash partial O (fp32)
__device__ float g_ml   [2 * NITEM * 256];    // flash partial (m,l)

__device__ __nv_bfloat16 g_hb  [MR * DD];
__device__ __nv_bfloat16 g_ob  [MR * DD];
__device__ __nv_bfloat16 g_ffb [MR * FF_];
__device__ __nv_bfloat16 g_qkvb[MR * D3];

__device__ __nv_bfloat16 g_wteb [VV * DD];
__device__ __nv_bfloat16 g_qkvT [LL * DD * D3];
__device__ __nv_bfloat16 g_projT[LL * DD * DD];
__device__ __nv_bfloat16 g_fc1T [LL * DD * FF_];
__device__ __nv_bfloat16 g_fc2T [LL * FF_ * DD];

// ================= low-level helpers (baseline PTX only) =================
__device__ __forceinline__ uint32_t smem_u32(const void* p) {
    uint32_t a;
    asm("{ .reg .u64 t; cvta.to.shared.u64 t, %1; cvt.u32.u64 %0, t; }" : "=r"(a) : "l"(p));
    return a;
}
__device__ __forceinline__ void cp_async16(uint32_t dst, const void* src, bool valid) {
    int sz = valid ? 16 : 0;
    asm volatile("cp.async.cg.shared.global [%0], [%1], 16, %2;"
                 :: "r"(dst), "l"(src), "r"(sz) : "memory");
}
#define CP_COMMIT()  asm volatile("cp.async.commit_group;" ::: "memory")
#define CP_WAIT(n)   asm volatile("cp.async.wait_group %0;" :: "n"(n) : "memory")

__device__ __forceinline__ void ldmatrix_x4(uint32_t& r0, uint32_t& r1,
                                            uint32_t& r2, uint32_t& r3, uint32_t addr) {
    asm volatile("ldmatrix.sync.aligned.m8n8.x4.shared.b16 {%0,%1,%2,%3}, [%4];"
                 : "=r"(r0), "=r"(r1), "=r"(r2), "=r"(r3) : "r"(addr));
}
__device__ __forceinline__ void ldmatrix_x4_trans(uint32_t& r0, uint32_t& r1,
                                                  uint32_t& r2, uint32_t& r3, uint32_t addr) {
    asm volatile("ldmatrix.sync.aligned.m8n8.x4.trans.shared.b16 {%0,%1,%2,%3}, [%4];"
                 : "=r"(r0), "=r"(r1), "=r"(r2), "=r"(r3) : "r"(addr));
}
__device__ __forceinline__ void mma_bf16(float* c, const uint32_t* a,
                                         uint32_t b0, uint32_t b1) {
    asm volatile(
        "mma.sync.aligned.m16n8k16.row.col.f32.bf16.bf16.f32 "
        "{%0,%1,%2,%3}, {%4,%5,%6,%7}, {%8,%9}, {%0,%1,%2,%3};"
        : "+f"(c[0]), "+f"(c[1]), "+f"(c[2]), "+f"(c[3])
        : "r"(a[0]), "r"(a[1]), "r"(a[2]), "r"(a[3]), "r"(b0), "r"(b1));
}
__device__ __forceinline__ uint32_t pack_bf16x2(float lo, float hi) {
    __nv_bfloat162 h = __floats2bfloat162_rn(lo, hi);
    return *reinterpret_cast<uint32_t*>(&h);
}
__device__ __forceinline__ void ms_update(float& m, float& s, float v) {
    if (v > m) { s = s * __expf(m - v) + 1.0f; m = v; }
    else       { s += __expf(v - m); }
}
__device__ __forceinline__ void ms_combine(float& m, float& s, float m2, float s2) {
    float mn = fmaxf(m, m2);
    float e1 = (m  > -INFINITY) ? __expf(m  - mn) : 0.f;
    float e2 = (m2 > -INFINITY) ? __expf(m2 - mn) : 0.f;
    s = s * e1 + s2 * e2;
    m = mn;
}

// ---------------- block reductions ----------------
__device__ __forceinline__ float blockReduceSum(float v) {
    __shared__ float sh[32];
    int lane = threadIdx.x & 31, wid = threadIdx.x >> 5;
    #pragma unroll
    for (int o = 16; o; o >>= 1) v += __shfl_xor_sync(0xffffffffu, v, o);
    __syncthreads();
    if (lane == 0) sh[wid] = v;
    __syncthreads();
    float r = (lane < (int)(blockDim.x >> 5)) ? sh[lane] : 0.f;
    if (wid == 0) {
        #pragma unroll
        for (int o = 16; o; o >>= 1) r += __shfl_xor_sync(0xffffffffu, r, o);
        if (lane == 0) sh[0] = r;
    }
    __syncthreads();
    return sh[0];
}
__device__ __forceinline__ float2 blockReduceSum2(float a, float b) {
    __shared__ float2 sh[8];
    int lane = threadIdx.x & 31, wid = threadIdx.x >> 5;
    #pragma unroll
    for (int o = 16; o; o >>= 1) {
        a += __shfl_xor_sync(0xffffffffu, a, o);
        b += __shfl_xor_sync(0xffffffffu, b, o);
    }
    if (lane == 0) sh[wid] = make_float2(a, b);
    __syncthreads();
    if (wid == 0) {
        float2 r = (lane < 8) ? sh[lane] : make_float2(0.f, 0.f);
        #pragma unroll
        for (int o = 4; o; o >>= 1) {
            r.x += __shfl_xor_sync(0xffffffffu, r.x, o);
            r.y += __shfl_xor_sync(0xffffffffu, r.y, o);
        }
        if (lane == 0) sh[0] = r;
    }
    __syncthreads();
    return sh[0];
}

// ---------------- weight prep ----------------
__global__ void transpose_to_bf16(const float* __restrict__ src,
                                  __nv_bfloat16* __restrict__ dst,
                                  int K, int N) {
    __shared__ float tile[64][65];
    const float* s = src + (size_t)blockIdx.z * K * N;
    __nv_bfloat16* d = dst + (size_t)blockIdx.z * K * N;
    int n0 = blockIdx.x * 64, k0 = blockIdx.y * 64;
    int tid = threadIdx.x;
    #pragma unroll
    for (int e = 0; e < 8; e++) {
        int idx = tid + e * 256;
        int r = idx >> 5, c = idx & 31;
        float2 v = *reinterpret_cast<const float2*>(s + (size_t)(k0 + r) * N + n0 + c * 2);
        tile[c * 2][r]     = v.x;
        tile[c * 2 + 1][r] = v.y;
    }
    __syncthreads();
    #pragma unroll
    for (int e = 0; e < 8; e++) {
        int idx = tid + e * 256;
        int r = idx >> 5, c = (idx & 31) * 2;
        __nv_bfloat162 v = __floats2bfloat162_rn(tile[r][c], tile[r][c + 1]);
        *reinterpret_cast<__nv_bfloat162*>(d + (size_t)(n0 + r) * K + k0 + c) = v;
    }
}

__global__ void convert_bf16_kernel4(const float4* __restrict__ src,
                                     __nv_bfloat162* __restrict__ dst, long n4) {
    long i = (long)blockIdx.x * blockDim.x + threadIdx.x;
    if (i < n4) {
        float4 v = src[i];
        dst[i * 2]     = __floats2bfloat162_rn(v.x, v.y);
        dst[i * 2 + 1] = __floats2bfloat162_rn(v.z, v.w);
    }
}

// ---------------- embedding (float2) ----------------
__global__ void embed_kernel(const int* __restrict__ tokens,
                             const float* __restrict__ wte,
                             const float* __restrict__ wpe,
                             float* __restrict__ x) {
    int i = blockIdx.x * blockDim.x + threadIdx.x;
    if (i >= MR * (DD / 2)) return;
    int row = i / (DD / 2), d2 = i - row * (DD / 2);
    int s = row & (SS - 1);
    float2 a = *reinterpret_cast<const float2*>(wte + (size_t)tokens[row] * DD + d2 * 2);
    float2 b = *reinterpret_cast<const float2*>(wpe + (size_t)s * DD + d2 * 2);
    *reinterpret_cast<float2*>(x + (size_t)row * DD + d2 * 2) = make_float2(a.x + b.x, a.y + b.y);
}

// ---------------- layernorm -> bf16 ----------------
__global__ void layernorm_kernel(const float* __restrict__ in,
                                 const float* __restrict__ g,
                                 const float* __restrict__ b,
                                 __nv_bfloat16* __restrict__ out) {
    int row = blockIdx.x;
    const float* x = in + (size_t)row * DD;
    int t = threadIdx.x;
    float v0 = x[t], v1 = x[t + 256], v2 = x[t + 512];
    float2 r = blockReduceSum2(v0 + v1 + v2, v0 * v0 + v1 * v1 + v2 * v2);
    float mu = r.x * (1.0f / 768.0f);
    float var = r.y * (1.0f / 768.0f) - mu * mu;
    float rstd = rsqrtf(var + 1e-5f);
    __nv_bfloat16* o = out + (size_t)row * DD;
    o[t]       = __float2bfloat16((v0 - mu) * rstd * g[t]       + b[t]);
    o[t + 256] = __float2bfloat16((v1 - mu) * rstd * g[t + 256] + b[t + 256]);
    o[t + 512] = __float2bfloat16((v2 - mu) * rstd * g[t + 512] + b[t + 512]);
}

// ================= mma.sync NT GEMM, single-barrier 3-stage pipeline ========
#define GBM 128
#define GBK 64
#define ROWB 144
#define ABUF 18432   // 128 * 144

template <bool FUSE, int BN, bool ATOMIC>
__global__ __launch_bounds__(256, 2)
void gemm_mma_kernel(const __nv_bfloat16* __restrict__ A,
                     const __nv_bfloat16* __restrict__ B,
                     float* __restrict__ Cf,
                     __nv_bfloat16* __restrict__ Cbf,
                     const float* __restrict__ bias,
                     const float* __restrict__ res,
                     int N, int K, int ldc, int act,
                     float* __restrict__ pm, float* __restrict__ ps) {
    constexpr int BBUF = BN * ROWB;
    constexpr int BUFS = ABUF + BBUF;
    constexpr int NNB  = BN / 32;
    extern __shared__ __align__(128) uint8_t gsm[];
    uint32_t sbase = smem_u32(gsm);
    int tid = threadIdx.x;
    int m0 = blockIdx.x * GBM, n0 = blockIdx.y * BN;
    int nk = K / GBK;
    int kbase = 0;
    if (ATOMIC) {
        nk = K / GBK / gridDim.z;
        kbase = blockIdx.z * nk;
    }

    auto issue = [&](int c) {
        int k0 = (kbase + c) * GBK;
        int st = c % 3;
        uint32_t dA = sbase + st * BUFS;
        uint32_t dB = dA + ABUF;
        #pragma unroll
        for (int e = 0; e < 4; e++) {
            int idx = tid + e * 256;
            int r = idx >> 3, cc = idx & 7;
            cp_async16(dA + r * ROWB + cc * 16,
                       A + (size_t)(m0 + r) * K + k0 + cc * 8, true);
        }
        #pragma unroll
        for (int e = 0; e < BN / 32; e++) {
            int idx = tid + e * 256;
            int r = idx >> 3, cc = idx & 7;
            int gn = n0 + r;
            cp_async16(dB + r * ROWB + cc * 16,
                       B + (size_t)gn * K + k0 + cc * 8, gn < N);
        }
        CP_COMMIT();
    };

    int warp = tid >> 5, lane = tid & 31;
    int wm = warp >> 1, wn = warp & 1;
    int lr = lane & 15, lc = lane >> 4;
    float acc[2][2 * NNB][4];
    #pragma unroll
    for (int i = 0; i < 2; i++)
        #pragma unroll
        for (int j = 0; j < 2 * NNB; j++)
            #pragma unroll
            for (int q = 0; q < 4; q++) acc[i][j][q] = 0.f;

    issue(0);
    if (nk > 1) issue(1);
    for (int c = 0; c < nk; c++) {
        if (c + 1 < nk) { CP_WAIT(1); } else { CP_WAIT(0); }
        __syncthreads();
        uint32_t aB = sbase + (c % 3) * BUFS;
        uint32_t bB = aB + ABUF;
        #pragma unroll
        for (int kk = 0; kk < 4; kk++) {
            uint32_t a[2][4];
            #pragma unroll
            for (int mi = 0; mi < 2; mi++) {
                uint32_t addr = aB + (uint32_t)((wm * 32 + mi * 16 + lr) * ROWB
                                                + (kk * 16 + lc * 8) * 2);
                ldmatrix_x4(a[mi][0], a[mi][1], a[mi][2], a[mi][3], addr);
            }
            #pragma unroll
            for (int nb = 0; nb < NNB; nb++) {
                uint32_t b0, b1, b2, b3;
                uint32_t addr = bB + (uint32_t)((wn * (BN / 2) + nb * 16 + lr) * ROWB
                                                + (kk * 16 + lc * 8) * 2);
                ldmatrix_x4(b0, b1, b2, b3, addr);
                #pragma unroll
                for (int mi = 0; mi < 2; mi++) {
                    mma_bf16(acc[mi][nb * 2],     a[mi], b0, b2);
                    mma_bf16(acc[mi][nb * 2 + 1], a[mi], b1, b3);
                }
            }
        }
        if (c + 2 < nk) issue(c + 2);
    }

    // --- epilogue ---
    int mrow = m0 + wm * 32;
    int ncol = n0 + wn * (BN / 2);
    int tr = lane >> 2, tc = (lane & 3) * 2;
    bool vec = ((ldc & 1) == 0);
    float tm[2][2], ts[2][2];
    if (FUSE) {
        #pragma unroll
        for (int i = 0; i < 2; i++)
            #pragma unroll
            for (int j = 0; j < 2; j++) { tm[i][j] = -INFINITY; ts[i][j] = 0.f; }
    }
    #pragma unroll
    for (int mi = 0; mi < 2; mi++) {
        #pragma unroll
        for (int ni = 0; ni < 2 * NNB; ni++) {
            #pragma unroll
            for (int h = 0; h < 2; h++) {
                int row = mrow + mi * 16 + tr + h * 8;
                int col = ncol + ni * 8 + tc;
                float v0 = acc[mi][ni][h * 2];
                float v1 = acc[mi][ni][h * 2 + 1];
                if (ATOMIC) {
                    if (bias && blockIdx.z == 0) {
                        v0 += bias[col];
                        if (col + 1 < N) v1 += bias[col + 1];
                    }
                    if (col < N)     atomicAdd(Cf + (size_t)row * ldc + col, v0);
                    if (col + 1 < N) atomicAdd(Cf + (size_t)row * ldc + col + 1, v1);
                    continue;
                }
                if (bias) { v0 += bias[col]; if (col + 1 < N) v1 += bias[col + 1]; }
                if (res) {
                    const float* rp = res + (size_t)row * ldc + col;
                    v0 += rp[0];
                    if (col + 1 < N) v1 += rp[1];
                }
                if (act) {
                    v0 = v0 * 0.5f * (1.0f + erff(v0 * 0.70710678118654752f));
                    v1 = v1 * 0.5f * (1.0f + erff(v1 * 0.70710678118654752f));
                }
                if (FUSE) {
                    if (col < N)     ms_update(tm[mi][h], ts[mi][h], v0);
                    if (col + 1 < N) ms_update(tm[mi][h], ts[mi][h], v1);
                }
                if (vec && col + 1 < N) {
                    if (Cf) *reinterpret_cast<float2*>(Cf + (size_t)row * ldc + col)
                                = make_float2(v0, v1);
                    else    *reinterpret_cast<__nv_bfloat162*>(Cbf + (size_t)row * ldc + col)
                                = __floats2bfloat162_rn(v0, v1);
                } else {
                    if (col < N) {
                        if (Cf) Cf[(size_t)row * ldc + col] = v0;
                        else    Cbf[(size_t)row * ldc + col] = __float2bfloat16(v0);
                    }
                    if (col + 1 < N) {
                        if (Cf) Cf[(size_t)row * ldc + col + 1] = v1;
                        else    Cbf[(size_t)row * ldc + col + 1] = __float2bfloat16(v1);
                    }
                }
            }
        }
    }
    if (FUSE) {
        float2* red = reinterpret_cast<float2*>(gsm);
        __syncthreads();
        #pragma unroll
        for (int mi = 0; mi < 2; mi++) {
            #pragma unroll
            for (int h = 0; h < 2; h++) {
                float m = tm[mi][h], s = ts[mi][h];
                #pragma unroll
                for (int o = 1; o <= 2; o <<= 1) {
                    float m2 = __shfl_xor_sync(0xffffffffu, m, o);
                    float s2 = __shfl_xor_sync(0xffffffffu, s, o);
                    ms_combine(m, s, m2, s2);
                }
                if ((lane & 3) == 0) {
                    int row_local = wm * 32 + mi * 16 + tr + h * 8;
                    red[row_local * 2 + wn] = make_float2(m, s);
                }
            }
        }
        __syncthreads();
        if (tid < 128) {
            float2 p0 = red[tid * 2], p1 = red[tid * 2 + 1];
            float m = p0.x, s = p0.y;
            ms_combine(m, s, p1.x, p1.y);
            pm[(size_t)(m0 + tid) * NT + blockIdx.y] = m;
            ps[(size_t)(m0 + tid) * NT + blockIdx.y] = s;
        }
    }
}

#define GS128 (3 * (ABUF + 128 * ROWB))   // 110592
#define GS64  (3 * (ABUF + 64 * ROWB))    // 82944

// ============ flash attention partial: split-KV, 3-stage, 1 barrier =========
#define FQROWB 144
#define FQ_OFF 0
#define FKV_OFF 18432
#define FSTAGE  18432
#define FSMEM   (FKV_OFF + 3 * FSTAGE)   // 73728

__global__ __launch_bounds__(256, 2)
void flash_partial_kernel(const __nv_bfloat16* __restrict__ qkv,
                          float* __restrict__ opart,
                          float* __restrict__ mlout) {
    extern __shared__ __align__(128) uint8_t fsm[];
    uint32_t sbase = smem_u32(fsm);
    int tid = threadIdx.x;
    int qt = blockIdx.x;
    int q0 = qt * 128;
    int bh = blockIdx.y, b = bh / HH, h = bh - b * HH;
    int split = blockIdx.z;
    const size_t rowbase = (size_t)b * SS * D3;
    const int qoff = h * DH, koff = DD + h * DH, voff = 2 * DD + h * DH;

    int nt = q0 / 64 + 2;         // always even
    int nh = nt >> 1;
    int ts = split * nh, te = ts + nh;

    auto issue_q = [&]() {
        #pragma unroll
        for (int e = 0; e < 4; e++) {
            int idx = tid + e * 256;
            int r = idx >> 3, c = idx & 7;
            cp_async16(sbase + FQ_OFF + r * FQROWB + c * 16,
                       qkv + rowbase + (size_t)(q0 + r) * D3 + qoff + c * 8, true);
        }
        CP_COMMIT();
    };
    auto issue_kv = [&](int t) {
        int kv0 = t * 64;
        uint32_t kd = sbase + FKV_OFF + ((t - ts) % 3) * FSTAGE;
        uint32_t vd = kd + 9216;
        #pragma unroll
        for (int e = 0; e < 2; e++) {
            int idx = tid + e * 256;
            int r = idx >> 3, c = idx & 7;
            const size_t g = rowbase + (size_t)(kv0 + r) * D3;
            cp_async16(kd + r * FQROWB + c * 16, qkv + g + koff + c * 8, true);
            cp_async16(vd + r * FQROWB + c * 16, qkv + g + voff + c * 8, true);
        }
        CP_COMMIT();
    };

    int warp = tid >> 5, lane = tid & 31;
    int lr = lane & 15, lc = lane >> 4;
    int tr = lane >> 2, qd = lane & 3;
    int wq = q0 + warp * 16;

    float of[8][4];
    #pragma unroll
    for (int i = 0; i < 8; i++)
        #pragma unroll
        for (int j = 0; j < 4; j++) of[i][j] = 0.f;
    float m0r = -INFINITY, m1r = -INFINITY, l0r = 0.f, l1r = 0.f;

    issue_q();
    issue_kv(ts);
    if (te - ts > 1) issue_kv(ts + 1);

    const float sc = 0.03608439182435161f;  // 1/sqrt(768)

    for (int t = ts; t < te; t++) {
        if (t + 1 < te) { CP_WAIT(1); } else { CP_WAIT(0); }
        __syncthreads();
        int kv0 = t * 64;
        uint32_t kB = sbase + FKV_OFF + ((t - ts) % 3) * FSTAGE;
        uint32_t vB = kB + 9216;

        float sf[8][4];
        #pragma unroll
        for (int i = 0; i < 8; i++)
            #pragma unroll
            for (int j = 0; j < 4; j++) sf[i][j] = 0.f;
        #pragma unroll
        for (int ks = 0; ks < 4; ks++) {
            uint32_t aq[4];
            uint32_t qa = sbase + FQ_OFF + (uint32_t)((warp * 16 + lr) * FQROWB
                                                      + (ks * 16 + lc * 8) * 2);
            ldmatrix_x4(aq[0], aq[1], aq[2], aq[3], qa);
            #pragma unroll
            for (int nb2 = 0; nb2 < 4; nb2++) {
                uint32_t b0, b1, b2, b3;
                uint32_t ka = kB + (uint32_t)((nb2 * 16 + lr) * FQROWB
                                              + (ks * 16 + lc * 8) * 2);
                ldmatrix_x4(b0, b1, b2, b3, ka);
                mma_bf16(sf[nb2 * 2],     aq, b0, b2);
                mma_bf16(sf[nb2 * 2 + 1], aq, b1, b3);
            }
        }
        #pragma unroll
        for (int i = 0; i < 8; i++)
            #pragma unroll
            for (int j = 0; j < 4; j++) sf[i][j] *= sc;
        if (kv0 + 63 > wq) {
            #pragma unroll
            for (int nb = 0; nb < 8; nb++) {
                #pragma unroll
                for (int j = 0; j < 4; j++) {
                    int col = kv0 + nb * 8 + qd * 2 + (j & 1);
                    int row = wq + tr + (j >> 1) * 8;
                    if (col > row) sf[nb][j] = -INFINITY;
                }
            }
        }
        float tm0 = -INFINITY, tm1 = -INFINITY;
        #pragma unroll
        for (int nb = 0; nb < 8; nb++) {
            tm0 = fmaxf(tm0, fmaxf(sf[nb][0], sf[nb][1]));
            tm1 = fmaxf(tm1, fmaxf(sf[nb][2], sf[nb][3]));
        }
        tm0 = fmaxf(tm0, __shfl_xor_sync(0xffffffffu, tm0, 1));
        tm0 = fmaxf(tm0, __shfl_xor_sync(0xffffffffu, tm0, 2));
        tm1 = fmaxf(tm1, __shfl_xor_sync(0xffffffffu, tm1, 1));
        tm1 = fmaxf(tm1, __shfl_xor_sync(0xffffffffu, tm1, 2));
        float mn0 = fmaxf(m0r, tm0), mn1 = fmaxf(m1r, tm1);
        float mnc0 = fmaxf(mn0, -1e30f), mnc1 = fmaxf(mn1, -1e30f);
        float f0 = __expf(m0r - mnc0), f1 = __expf(m1r - mnc1);
        m0r = mn0; m1r = mn1;
        float rs0 = 0.f, rs1 = 0.f;
        #pragma unroll
        for (int nb = 0; nb < 8; nb++) {
            sf[nb][0] = __expf(sf[nb][0] - mnc0);
            sf[nb][1] = __expf(sf[nb][1] - mnc0);
            sf[nb][2] = __expf(sf[nb][2] - mnc1);
            sf[nb][3] = __expf(sf[nb][3] - mnc1);
            rs0 += sf[nb][0] + sf[nb][1];
            rs1 += sf[nb][2] + sf[nb][3];
        }
        rs0 += __shfl_xor_sync(0xffffffffu, rs0, 1);
        rs0 += __shfl_xor_sync(0xffffffffu, rs0, 2);
        rs1 += __shfl_xor_sync(0xffffffffu, rs1, 1);
        rs1 += __shfl_xor_sync(0xffffffffu, rs1, 2);
        l0r = l0r * f0 + rs0;
        l1r = l1r * f1 + rs1;
        #pragma unroll
        for (int nb = 0; nb < 8; nb++) {
            of[nb][0] *= f0; of[nb][1] *= f0;
            of[nb][2] *= f1; of[nb][3] *= f1;
        }
        #pragma unroll
        for (int ks = 0; ks < 4; ks++) {
            uint32_t ap[4];
            ap[0] = pack_bf16x2(sf[2 * ks][0],     sf[2 * ks][1]);
            ap[1] = pack_bf16x2(sf[2 * ks][2],     sf[2 * ks][3]);
            ap[2] = pack_bf16x2(sf[2 * ks + 1][0], sf[2 * ks + 1][1]);
            ap[3] = pack_bf16x2(sf[2 * ks + 1][2], sf[2 * ks + 1][3]);
            #pragma unroll
            for (int nb2 = 0; nb2 < 4; nb2++) {
                int g = lane >> 3;
                int kvr = ks * 16 + (g & 1) * 8 + (lane & 7);
                int dhc = nb2 * 16 + (g >> 1) * 8;
                uint32_t va = vB + (uint32_t)(kvr * FQROWB + dhc * 2);
                uint32_t r0, r1, r2, r3;
                ldmatrix_x4_trans(r0, r1, r2, r3, va);
                mma_bf16(of[nb2 * 2],     ap, r0, r1);
                mma_bf16(of[nb2 * 2 + 1], ap, r2, r3);
            }
        }
        if (t + 2 < te) issue_kv(t + 2);
    }

    // ---- write unnormalized partials ----
    int item = bh * NQT + qt;
    float* op = opart + ((size_t)split * NITEM + item) * 8192;
    float* ml = mlout + ((size_t)split * NITEM + item) * 256;
    #pragma unroll
    for (int nb = 0; nb < 8; nb++) {
        int col = nb * 8 + qd * 2;
        int r0 = warp * 16 + tr, r1 = r0 + 8;
        *reinterpret_cast<float2*>(op + r0 * 64 + col) = make_float2(of[nb][0], of[nb][1]);
        *reinterpret_cast<float2*>(op + r1 * 64 + col) = make_float2(of[nb][2], of[nb][3]);
    }
    if (qd == 0) {
        int r0 = warp * 16 + tr, r1 = r0 + 8;
        *reinterpret_cast<float2*>(ml + r0 * 2) = make_float2(m0r, l0r);
        *reinterpret_cast<float2*>(ml + r1 * 2) = make_float2(m1r, l1r);
    }
}

// ---- merge the two KV splits ----
__global__ __launch_bounds__(256)
void flash_merge_kernel(const float* __restrict__ opart,
                        const float* __restrict__ ml,
                        __nv_bfloat16* __restrict__ o) {
    __shared__ float sf0[128], sf1[128], sinv[128];
    int item = blockIdx.x;
    int bh = item / NQT, qt = item - bh * NQT;
    int b = bh / HH, h = bh - b * HH;
    int tid = threadIdx.x;
    if (tid < 128) {
        float2 p0 = *reinterpret_cast<const float2*>(ml + (size_t)item * 256 + tid * 2);
        float2 p1 = *reinterpret_cast<const float2*>(ml + ((size_t)NITEM + item) * 256 + tid * 2);
        float m = fmaxf(p0.x, p1.x);
        float e0 = (p0.x > -1e30f) ? __expf(p0.x - m) : 0.f;
        float e1 = (p1.x > -1e30f) ? __expf(p1.x - m) : 0.f;
        float l = p0.y * e0 + p1.y * e1;
        sf0[tid] = e0; sf1[tid] = e1; sinv[tid] = 1.0f / l;
    }
    __syncthreads();
    const float* O0 = opart + (size_t)item * 8192;
    const float* O1 = opart + ((size_t)NITEM + item) * 8192;
    size_t obase = (size_t)b * SS * DD + (size_t)(qt * 128) * DD + (size_t)h * DH;
    for (int e = tid; e < 4096; e += 256) {
        int row = e >> 5, cp = (e & 31) * 2;
        float2 a = *reinterpret_cast<const float2*>(O0 + row * 64 + cp);
        float2 c = *reinterpret_cast<const float2*>(O1 + row * 64 + cp);
        float w0 = sf0[row], w1 = sf1[row], iv = sinv[row];
        __nv_bfloat162 v = __floats2bfloat162_rn((a.x * w0 + c.x * w1) * iv,
                                                 (a.y * w0 + c.y * w1) * iv);
        *reinterpret_cast<__nv_bfloat162*>(o + obase + (size_t)row * DD + cp) = v;
    }
}

// ---- finish log_softmax from GEMM partials ---------------------------------
__global__ __launch_bounds__(512)
void logsoftmax_finish_kernel(float* __restrict__ logits,
                              const float* __restrict__ pm,
                              const float* __restrict__ ps,
                              const int* __restrict__ target,
                              float* __restrict__ picked) {
    __shared__ float shm[16], shs[16], bc[1];
    int row = blockIdx.x;
    float* x = logits + (size_t)row * VV;
    int t = threadIdx.x, lane = t & 31, wid = t >> 5;

    float m = -INFINITY, s = 0.f;
    const float* pmr = pm + (size_t)row * NT;
    const float* psr = ps + (size_t)row * NT;
    for (int i = t; i < NT; i += 512)
        ms_combine(m, s, pmr[i], psr[i]);
    #pragma unroll
    for (int o = 16; o; o >>= 1) {
        float m2 = __shfl_xor_sync(0xffffffffu, m, o);
        float s2 = __shfl_xor_sync(0xffffffffu, s, o);
        ms_combine(m, s, m2, s2);
    }
    if (lane == 0) { shm[wid] = m; shs[wid] = s; }
    __syncthreads();
    if (t == 0) {
        float M = shm[0], S = shs[0];
        #pragma unroll
        for (int i = 1; i < 16; i++)
            ms_combine(M, S, shm[i], shs[i]);
        bc[0] = M + logf(S);
    }
    __syncthreads();
    float sub = bc[0];
    int tgt = target[row];

    int head = (int)(((16 - ((uintptr_t)x & 15)) & 15) >> 2);
    int nvec = (VV - head) >> 2;
    float* xv = x + head;
    for (int i = t; i < head; i += 512) {
        float lp = x[i] - sub;
        x[i] = lp;
        if (i == tgt) picked[row] = lp;
    }
    for (int i = t; i < nvec; i += 512) {
        float4 v = *reinterpret_cast<const float4*>(xv + i * 4);
        v.x -= sub; v.y -= sub; v.z -= sub; v.w -= sub;
        *reinterpret_cast<float4*>(xv + i * 4) = v;
        int base = head + i * 4;
        if (tgt >= base && tgt < base + 4) {
            float pv = (tgt == base) ? v.x : (tgt == base + 1) ? v.y
                     : (tgt == base + 2) ? v.z : v.w;
            picked[row] = pv;
        }
    }
    for (int i = head + nvec * 4 + t; i < VV; i += 512) {
        float lp = x[i] - sub;
        x[i] = lp;
        if (i == tgt) picked[row] = lp;
    }
}

__global__ void finalize_loss_kernel(const float* __restrict__ picked,
                                     float* __restrict__ out) {
    float s = 0.f;
    for (int i = threadIdx.x; i < MR; i += 256) s += picked[i];
    s = blockReduceSum(s);
    if (threadIdx.x == 0) out[(size_t)MR * VV] = -s * (1.0f / (float)MR);
}

// ---------------- host orchestration ----------------
extern "C" void kernel_launch(void* const* d_in, const int* in_sizes, int n_in,
                              void* d_out, int out_size) {
    const int*   tokens = (const int*)  d_in[0];
    const int*   target = (const int*)  d_in[1];
    const float* wte    = (const float*)d_in[2];
    const float* wpe    = (const float*)d_in[3];
    const float* ln1_g  = (const float*)d_in[4];
    const float* ln1_b  = (const float*)d_in[5];
    const float* qkv_w  = (const float*)d_in[6];
    const float* qkv_b  = (const float*)d_in[7];
    const float* proj_w = (const float*)d_in[8];
    const float* proj_b = (const float*)d_in[9];
    const float* ln2_g  = (const float*)d_in[10];
    const float* ln2_b  = (const float*)d_in[11];
    const float* fc1_w  = (const float*)d_in[12];
    const float* fc1_b  = (const float*)d_in[13];
    const float* fc2_w  = (const float*)d_in[14];
    const float* fc2_b  = (const float*)d_in[15];
    const float* lnf_g  = (const float*)d_in[16];
    const float* lnf_b  = (const float*)d_in[17];
    float* out = (float*)d_out;

    float *gx, *gpicked, *gpm, *gps, *gopart, *gml;
    __nv_bfloat16 *ghb, *gob, *gffb, *gqkvb, *gwteb, *gqkvT, *gprojT, *gfc1T, *gfc2T;
    cudaGetSymbolAddress((void**)&gx,     g_x);
    cudaGetSymbolAddress((void**)&gpicked,g_picked);
    cudaGetSymbolAddress((void**)&gpm,    g_pm);
    cudaGetSymbolAddress((void**)&gps,    g_ps);
    cudaGetSymbolAddress((void**)&gopart, g_opart);
    cudaGetSymbolAddress((void**)&gml,    g_ml);
    cudaGetSymbolAddress((void**)&ghb,    g_hb);
    cudaGetSymbolAddress((void**)&gob,    g_ob);
    cudaGetSymbolAddress((void**)&gffb,   g_ffb);
    cudaGetSymbolAddress((void**)&gqkvb,  g_qkvb);
    cudaGetSymbolAddress((void**)&gwteb,  g_wteb);
    cudaGetSymbolAddress((void**)&gqkvT,  g_qkvT);
    cudaGetSymbolAddress((void**)&gprojT, g_projT);
    cudaGetSymbolAddress((void**)&gfc1T,  g_fc1T);
    cudaGetSymbolAddress((void**)&gfc2T,  g_fc2T);

    cudaFuncSetAttribute(flash_partial_kernel,
                         cudaFuncAttributeMaxDynamicSharedMemorySize, FSMEM);
    cudaFuncSetAttribute(gemm_mma_kernel<false, 128, false>,
                         cudaFuncAttributeMaxDynamicSharedMemorySize, GS128);
    cudaFuncSetAttribute(gemm_mma_kernel<true, 128, false>,
                         cudaFuncAttributeMaxDynamicSharedMemorySize, GS128);
    cudaFuncSetAttribute(gemm_mma_kernel<false, 64, false>,
                         cudaFuncAttributeMaxDynamicSharedMemorySize, GS64);
    cudaFuncSetAttribute(gemm_mma_kernel<false, 64, true>,
                         cudaFuncAttributeMaxDynamicSharedMemorySize, GS64);

    {
        long n4 = (long)VV * DD / 4;
        convert_bf16_kernel4<<<(int)((n4 + 255) / 256), 256>>>(
            (const float4*)wte, (__nv_bfloat162*)gwteb, n4);
    }
    transpose_to_bf16<<<dim3(D3 / 64,  DD / 64,  LL), 256>>>(qkv_w,  gqkvT,  DD,  D3);
    transpose_to_bf16<<<dim3(DD / 64,  DD / 64,  LL), 256>>>(proj_w, gprojT, DD,  DD);
    transpose_to_bf16<<<dim3(FF_ / 64, DD / 64,  LL), 256>>>(fc1_w,  gfc1T,  DD,  FF_);
    transpose_to_bf16<<<dim3(DD / 64,  FF_ / 64, LL), 256>>>(fc2_w,  gfc2T,  FF_, DD);

    embed_kernel<<<(MR * (DD / 2) + 255) / 256, 256>>>(tokens, wte, wpe, gx);

    for (int l = 0; l < LL; l++) {
        layernorm_kernel<<<MR, 256>>>(gx, ln1_g + (size_t)l * DD, ln1_b + (size_t)l * DD, ghb);

        gemm_mma_kernel<false, 128, false><<<dim3(MR / GBM, D3 / 128), 256, GS128>>>(
            ghb, gqkvT + (size_t)l * DD * D3, nullptr, gqkvb,
            qkv_b + (size_t)l * D3, nullptr, D3, DD, D3, 0, nullptr, nullptr);

        flash_partial_kernel<<<dim3(NQT, BB * HH, 2), 256, FSMEM>>>(gqkvb, gopart, gml);
        flash_merge_kernel<<<NITEM, 256>>>(gopart, gml, gob);

        // proj: split-K=3, atomic accumulate into gx (gx holds residual)
        gemm_mma_kernel<false, 64, true><<<dim3(MR / GBM, DD / 64, 3), 256, GS64>>>(
            gob, gprojT + (size_t)l * DD * DD, gx, nullptr,
            proj_b + (size_t)l * DD, nullptr, DD, DD, DD, 0, nullptr, nullptr);

        layernorm_kernel<<<MR, 256>>>(gx, ln2_g + (size_t)l * DD, ln2_b + (size_t)l * DD, ghb);

        gemm_mma_kernel<false, 64, false><<<dim3(MR / GBM, FF_ / 64), 256, GS64>>>(
            ghb, gfc1T + (size_t)l * DD * FF_, nullptr, gffb,
            fc1_b + (size_t)l * FF_, nullptr, FF_, DD, FF_, 1, nullptr, nullptr);

        // fc2: split-K=3, atomic accumulate into gx
        gemm_mma_kernel<false, 64, true><<<dim3(MR / GBM, DD / 64, 3), 256, GS64>>>(
            gffb, gfc2T + (size_t)l * FF_ * DD, gx, nullptr,
            fc2_b + (size_t)l * DD, nullptr, DD, FF_, DD, 0, nullptr, nullptr);
    }

    layernorm_kernel<<<MR, 256>>>(gx, lnf_g, lnf_b, ghb);

    gemm_mma_kernel<true, 128, false><<<dim3(MR / GBM, NT), 256, GS128>>>(
        ghb, gwteb, out, nullptr, nullptr, nullptr, VV, DD, VV, 0, gpm, gps);

    logsoftmax_finish_kernel<<<MR, 512>>>(out, gpm, gps, target, gpicked);
    finalize_loss_kernel<<<1, 256>>>(gpicked, out);
}